// round 15
// baseline (speedup 1.0000x reference)
#include <cuda_runtime.h>
#include <cuda_bf16.h>
#include <cstdint>

#define Nn     100000
#define Ee     3200000
#define FEATS  256
#define CLS    16
#define HID    64
#define DEPTH  20
#define A1W_STRIDE (257*64)

#define FILL_BLOCKS 12500
#define MLP_BLOCKS  1563

#define PBLK   888     // persistent grid: 6 blocks/SM * 148 SMs
#define CHUNK  113     // ceil(Nn / PBLK)

#define BS_STRIDE 260  // B smem row stride (words), 1040B = 16B-aligned

// ---------------- scratch (static device globals; no allocation) ----------------
__device__ int      g_is64;
__device__ int      g_deg[Nn];       // must be zero at entry; persist chain2 re-zeroes
__device__ int      g_partial[PBLK];
__device__ int      g_rowptr[Nn + 1];
__device__ int      g_cursor[Nn];
__device__ int      g_col[Ee];       // src*16 sorted by dst (CSR by dst, float-index pre-scaled)
__device__ float    g_dis[Nn];
__device__ float    g_dis2[Nn];
__device__ float    g_h0[Nn * CLS];
__device__ float    g_hA[Nn * CLS];
__device__ float    g_out0[Nn * CLS];
__device__ float    g_dh0[Nn * CLS];
__device__ float    g_gA[Nn * CLS];
__device__ float    g_gB[Nn * CLS];
__device__ uint32_t g_xbf[Nn * 128];        // x packed bf16x2: [node][kpair]
__device__ uint32_t g_bw[CLS * 128 * 64];   // A1w packed bf16x2: [class][kpair][h]

__device__ int          g_bar_count;
__device__ volatile int g_bar_sense;

// ---------------- helpers ----------------
__device__ __forceinline__ uint32_t pack_bf16(float lo, float hi) {
    __nv_bfloat162 h = __floats2bfloat162_rn(lo, hi);
    return *reinterpret_cast<uint32_t*>(&h);
}

__device__ __forceinline__ uint32_t smem_u32(const void* p) {
    return (uint32_t)__cvta_generic_to_shared(p);
}

__device__ __forceinline__ void cp16(uint32_t dst, const void* src, int sz) {
    asm volatile("cp.async.ca.shared.global [%0], [%1], 16, %2;"
                 :: "r"(dst), "l"(src), "r"(sz));
}

// scalar random gather: bypass L1 allocation so per-block CSR state stays resident
__device__ __forceinline__ float ld_na_f(const float* p) {
    float v;
    asm("ld.global.nc.L1::no_allocate.f32 %0, [%1];" : "=f"(v) : "l"(p));
    return v;
}

__device__ __forceinline__ void grid_sync(int* sense) {
    __syncthreads();
    if (threadIdx.x == 0) {
        int s = *sense ^ 1;
        *sense = s;
        __threadfence();
        if (atomicAdd(&g_bar_count, 1) == PBLK - 1) {
            g_bar_count = 0;
            __threadfence();
            g_bar_sense = s;
        } else {
            while (g_bar_sense != s) __nanosleep(128);
            __threadfence();
        }
    }
    __syncthreads();
}

// ------ persistent degree histogram + scan + bf16 pre-pack (one launch) ------
__global__ __launch_bounds__(256, 6) void degscan_kernel(
    const void* __restrict__ edges, const float* __restrict__ x,
    const float* __restrict__ A1w) {
    __shared__ int s_is64, s_sense, s_off;
    __shared__ int s_red[8];
    __shared__ int s_w[4];
    int tid = threadIdx.x;
    int lane = tid & 31, warp = tid >> 5;
    const int* e32 = (const int*)edges;

    if (tid < 32) {
        int nz = 0;
        for (int i = tid; i < 2048; i += 32) nz += (e32[2 * i + 1] != 0);
        for (int o = 16; o; o >>= 1) nz += __shfl_down_sync(0xffffffffu, nz, o);
        if (tid == 0) {
            s_is64 = (nz == 0) ? 1 : 0;
            if (blockIdx.x == 0) g_is64 = s_is64;
        }
    }
    if (tid == 0) s_sense = g_bar_sense;
    __syncthreads();
    int sense = s_sense;
    int is64 = s_is64;

    // phase A: degree histogram (grid-stride) + bf16 pre-pack of x and A1w
    if (is64) {
        const long long* e64 = (const long long*)edges;
        for (long long e = (long long)blockIdx.x * 256 + tid; e < Ee; e += (long long)PBLK * 256)
            atomicAdd(&g_deg[(int)e64[Ee + e]], 1);
    } else {
        for (int e = blockIdx.x * 256 + tid; e < Ee; e += PBLK * 256)
            atomicAdd(&g_deg[e32[Ee + e]], 1);
    }
    for (int i = blockIdx.x * 256 + tid; i < Nn * 128; i += PBLK * 256) {
        float2 v = reinterpret_cast<const float2*>(x)[i];
        g_xbf[i] = pack_bf16(v.x, v.y);
    }
    for (int i = blockIdx.x * 256 + tid; i < CLS * 128 * 64; i += PBLK * 256) {
        int h = i & 63;
        int kp = (i >> 6) & 127;
        int cl = i >> 13;
        size_t base = (size_t)cl * A1W_STRIDE + (size_t)(1 + 2 * kp) * HID + h;
        g_bw[i] = pack_bf16(A1w[base], A1w[base + HID]);
    }
    grid_sync(&sense);

    // phase B1: per-block partial degree sums
    int lo = blockIdx.x * CHUNK;
    int hi = min(lo + CHUNK, Nn);
    int n = lo + tid;
    int v = (tid < 128 && n < hi) ? g_deg[n] : 0;
    {
        int r = v;
        for (int o = 16; o; o >>= 1) r += __shfl_down_sync(0xffffffffu, r, o);
        if (lane == 0 && warp < 4) s_red[warp] = r;
    }
    __syncthreads();
    if (tid == 0) g_partial[blockIdx.x] = s_red[0] + s_red[1] + s_red[2] + s_red[3];
    grid_sync(&sense);

    // phase B2: global offset + local exclusive scan + outputs
    {
        int ps = 0;
        for (int i = tid; i < blockIdx.x; i += 256) ps += g_partial[i];
        for (int o = 16; o; o >>= 1) ps += __shfl_down_sync(0xffffffffu, ps, o);
        if (lane == 0) s_red[warp] = ps;
    }
    __syncthreads();
    if (tid == 0) {
        int t = 0;
        for (int w = 0; w < 8; w++) t += s_red[w];
        s_off = t;
    }
    __syncthreads();
    int incl = v;
    for (int o = 1; o < 32; o <<= 1) {
        int u = __shfl_up_sync(0xffffffffu, incl, o);
        if (lane >= o) incl += u;
    }
    if (lane == 31 && warp < 4) s_w[warp] = incl;
    __syncthreads();
    if (tid < 128 && n < hi) {
        int woff = 0;
        for (int w = 0; w < warp; w++) woff += s_w[w];
        int excl = s_off + woff + incl - v;
        g_rowptr[n] = excl;
        g_cursor[n] = excl;
        float dv = (v > 0) ? rsqrtf((float)v) : 0.0f;
        g_dis[n] = dv;
        g_dis2[n] = dv * dv;
        if (n + 1 == Nn) g_rowptr[Nn] = excl + v;
    }
}

// ---------------- merged fill (CSR scatter, pre-scaled src*16) + MLP ----------------
#define MLP_NB 64
__global__ __launch_bounds__(256) void fillmlp_kernel(
    const void* __restrict__ edges,
    const float* __restrict__ x, const float* __restrict__ W1,
    const float* __restrict__ b1, const float* __restrict__ W2,
    const float* __restrict__ b2) {
    __shared__ float xs[MLP_NB][65];
    __shared__ float w1s[64][64];
    __shared__ float w2s[64][16];

    int m = blockIdx.x / 9, r = blockIdx.x % 9;
    int tid = threadIdx.x;

    if (r < 8) {
        int fb = m * 8 + r;
        if (fb >= FILL_BLOCKS) return;
        int e = fb * 256 + tid;
        if (e < Ee) {
            int is64 = g_is64;
            int s, d;
            if (is64) {
                s = (int)((const long long*)edges)[e];
                d = (int)((const long long*)edges)[(long long)Ee + e];
            } else {
                s = ((const int*)edges)[e];
                d = ((const int*)edges)[Ee + e];
            }
            int p = atomicAdd(&g_cursor[d], 1);
            g_col[p] = s * 16;   // pre-scaled float index of g-row
        }
        return;
    }

    if (m >= MLP_BLOCKS) return;
    int n0 = m * MLP_NB;
    int nq = tid >> 4;
    int jq = tid & 15;

    for (int i = tid; i < 64 * 16; i += 256) w2s[i >> 4][i & 15] = W2[i];

    float acc[4][4];
#pragma unroll
    for (int i = 0; i < 4; i++)
#pragma unroll
        for (int j = 0; j < 4; j++) acc[i][j] = 0.0f;

    for (int kc = 0; kc < FEATS; kc += 64) {
        for (int i = tid; i < 64 * 64; i += 256) {
            int n = i >> 6, k = i & 63;
            int gn = n0 + n;
            xs[n][k] = (gn < Nn) ? x[(size_t)gn * FEATS + kc + k] : 0.0f;
        }
        for (int i = tid; i < 64 * 64; i += 256) {
            int k = i >> 6, j = i & 63;
            w1s[k][j] = W1[(size_t)(kc + k) * HID + j];
        }
        __syncthreads();
#pragma unroll 8
        for (int k = 0; k < 64; k++) {
            float xv0 = xs[nq * 4 + 0][k];
            float xv1 = xs[nq * 4 + 1][k];
            float xv2 = xs[nq * 4 + 2][k];
            float xv3 = xs[nq * 4 + 3][k];
            float4 w = *reinterpret_cast<const float4*>(&w1s[k][jq * 4]);
            acc[0][0] += xv0 * w.x; acc[0][1] += xv0 * w.y; acc[0][2] += xv0 * w.z; acc[0][3] += xv0 * w.w;
            acc[1][0] += xv1 * w.x; acc[1][1] += xv1 * w.y; acc[1][2] += xv1 * w.z; acc[1][3] += xv1 * w.w;
            acc[2][0] += xv2 * w.x; acc[2][1] += xv2 * w.y; acc[2][2] += xv2 * w.z; acc[2][3] += xv2 * w.w;
            acc[3][0] += xv3 * w.x; acc[3][1] += xv3 * w.y; acc[3][2] += xv3 * w.z; acc[3][3] += xv3 * w.w;
        }
        __syncthreads();
    }
#pragma unroll
    for (int j = 0; j < 4; j++) {
        float bb = b1[jq * 4 + j];
#pragma unroll
        for (int i = 0; i < 4; i++)
            xs[nq * 4 + i][jq * 4 + j] = fmaxf(acc[i][j] + bb, 0.0f);
    }
    __syncthreads();
#pragma unroll
    for (int rr = 0; rr < 4; rr++) {
        int idx = tid * 4 + rr;
        int n = idx >> 4, c = idx & 15;
        float s = b2[c];
#pragma unroll 8
        for (int k = 0; k < 64; k++) s += xs[n][k] * w2s[k][c];
        int gn = n0 + n;
        if (gn < Nn) {
            float gv = g_dis[gn] * s;
            g_h0[gn * CLS + c] = s;
            g_gA[gn * CLS + c] = gv;
            g_dh0[gn * CLS + c] = gv;
        }
    }
}

// ---------------- persistent diffusion chain: pair-scalar gathers ----------------
// lane = (slot s in {0,1}, channel ch 0..15). One gather LDG covers TWO edges:
// lanes 0-15 read the full 64B g-row of edge eA (one channel/lane), lanes 16-31
// read edge eB's row -> 2 lines/instr instead of 8 (less within-LDG replay).
// 4 pairs (8 edges) unrolled per loop iteration -> 4 independent gathers in flight.
__global__ __launch_bounds__(256, 6) void persist_diffuse(int d2, float* __restrict__ h_ext) {
    __shared__ int s_sense;
    int tid = threadIdx.x;
    int warp = tid >> 5;
    int lane = tid & 31;
    int sl = lane >> 4;    // edge slot within pair: 0/1
    int ch = lane & 15;    // channel 0..15

    int lo = blockIdx.x * CHUNK;
    int hi = min(lo + CHUNK, Nn);

    if (tid == 0) s_sense = g_bar_sense;
    __syncthreads();
    int sense = s_sense;

    for (int it = 0; it < DEPTH; it++) {
        const float* __restrict__ gi = (it & 1) ? g_gB : g_gA;
        float* __restrict__ go = (it & 1) ? g_gA : g_gB;
        bool fin = (it == DEPTH - 1);

        for (int node = lo + warp; node < hi; node += 8) {
            int r0 = __ldg(&g_rowptr[node]);
            int r1 = __ldg(&g_rowptr[node + 1]);

            float a0 = 0.f, a1 = 0.f;
            int e = r0;
            // main: 8 edges (4 pairs) per iteration
            for (; e + 8 <= r1; e += 8) {
                int c0 = __ldg(&g_col[e + sl]);
                int c1 = __ldg(&g_col[e + 2 + sl]);
                int c2 = __ldg(&g_col[e + 4 + sl]);
                int c3 = __ldg(&g_col[e + 6 + sl]);
                float v0 = ld_na_f(gi + c0 + ch);
                float v1 = ld_na_f(gi + c1 + ch);
                float v2 = ld_na_f(gi + c2 + ch);
                float v3 = ld_na_f(gi + c3 + ch);
                a0 += v0; a1 += v1; a0 += v2; a1 += v3;
            }
            // remainder: up to 7 edges, one pair (or partial pair) at a time
            for (; e < r1; e += 2) {
                int idx = e + sl;
                bool act = (idx < r1);
                int c = __ldg(&g_col[act ? idx : r1 - 1]);
                float v = ld_na_f(gi + c + ch);
                if (act) a0 += v;
            }
            float acc = a0 + a1;
            acc += __shfl_xor_sync(0xffffffffu, acc, 16);   // combine the two slots

            if (sl == 0) {
                int oi = node * CLS + ch;
                if (!fin) {
                    float dd = __ldg(&g_dis2[node]);
                    go[oi] = 0.9f * dd * acc + 0.1f * g_dh0[oi];
                } else {
                    float dv = __ldg(&g_dis[node]);
                    const float* h0 = d2 ? g_out0 : g_h0;
                    float* ho = d2 ? h_ext : g_hA;
                    ho[oi] = 0.9f * dv * acc + 0.1f * h0[oi];
                }
            }
        }
        if (it != DEPTH - 1) grid_sync(&sense);
    }
    if (d2) {
        int n = blockIdx.x * 256 + tid;
        if (n < Nn) g_deg[n] = 0;
    }
}

// ------- fused head: bf16 MMA, cp.async double-buffered, 32x64 warp tiles ----
__global__ __launch_bounds__(256, 2) void head_kernel(
    const float* __restrict__ A1w, const float* __restrict__ A1b,
    const float* __restrict__ A2w, const float* __restrict__ A2b) {
    __shared__ uint32_t As32[2][64 * 20];        // [buf][row*20 + kword]
    __shared__ uint32_t Bs32[2][16 * BS_STRIDE]; // [buf][kpair*260 + col]
    __shared__ float a1w0s[4 * 64];
    __shared__ float a1bs[4 * 64];
    __shared__ float a2ws[4 * 64];
    __shared__ float outsum[64 * 4];

    int tid = threadIdx.x;
    int warp = tid >> 5, lane = tid & 31;
    int g = lane >> 2, q = lane & 3;
    int warp_m = warp & 1;    // 0..1 -> 32-row half
    int warp_n = warp >> 1;   // 0..3 -> class / 64-col quarter
    int n0 = blockIdx.x * 64;
    int c0 = blockIdx.y * 4;

    for (int i = tid; i < 256; i += 256) {
        int cl = i >> 6, h = i & 63;
        a1w0s[i] = A1w[(size_t)(c0 + cl) * A1W_STRIDE + h];
        a1bs[i]  = A1b[(c0 + cl) * HID + h];
        a2ws[i]  = A2w[(c0 + cl) * HID + h];
    }

    int a_row = tid >> 2, a_w4 = tid & 3;
    int a_gn = n0 + a_row;
    int a_sz = (a_gn < Nn) ? 16 : 0;
    const uint32_t* a_src_base = g_xbf + (size_t)min(a_gn, Nn - 1) * 128 + a_w4 * 4;
    uint32_t a_dst_off = (a_row * 20 + a_w4 * 4) * 4;

    uint32_t b_dst_off[4];
    const uint32_t* b_src_base[4];
#pragma unroll
    for (int j = 0; j < 4; j++) {
        int u = tid + j * 256;
        int kp = u >> 6, cl = (u >> 4) & 3, h4 = u & 15;
        b_dst_off[j] = (kp * BS_STRIDE + cl * 64 + h4 * 4) * 4;
        b_src_base[j] = g_bw + ((size_t)(c0 + cl) * 128 + kp) * 64 + h4 * 4;
    }

    uint32_t As_base = smem_u32(&As32[0][0]);
    uint32_t Bs_base = smem_u32(&Bs32[0][0]);
    const uint32_t A_BUF = 64 * 20 * 4;
    const uint32_t B_BUF = 16 * BS_STRIDE * 4;

    float acc[16][4];   // [s*8 + nt][4]
#pragma unroll
    for (int i = 0; i < 16; i++)
#pragma unroll
        for (int j = 0; j < 4; j++) acc[i][j] = 0.0f;

    {
        cp16(As_base + a_dst_off, a_src_base, a_sz);
#pragma unroll
        for (int j = 0; j < 4; j++) cp16(Bs_base + b_dst_off[j], b_src_base[j], 16);
        asm volatile("cp.async.commit_group;");
    }

    for (int c = 0; c < 8; c++) {
        if (c + 1 < 8) {
            int nb = (c + 1) & 1;
            cp16(As_base + nb * A_BUF + a_dst_off, a_src_base + (c + 1) * 16, a_sz);
#pragma unroll
            for (int j = 0; j < 4; j++)
                cp16(Bs_base + nb * B_BUF + b_dst_off[j], b_src_base[j] + (size_t)(c + 1) * 1024, 16);
            asm volatile("cp.async.commit_group;");
            asm volatile("cp.async.wait_group 1;");
        } else {
            asm volatile("cp.async.wait_group 0;");
        }
        __syncthreads();

        const uint32_t* As = As32[c & 1];
        const uint32_t* Bs = Bs32[c & 1];
#pragma unroll
        for (int kk = 0; kk < 2; kk++) {
            int kw = kk * 8;
            uint32_t af[2][4];
#pragma unroll
            for (int s = 0; s < 2; s++) {
                int ar = warp_m * 32 + s * 16;
                af[s][0] = As[(ar + g) * 20 + kw + q];
                af[s][1] = As[(ar + g + 8) * 20 + kw + q];
                af[s][2] = As[(ar + g) * 20 + kw + q + 4];
                af[s][3] = As[(ar + g + 8) * 20 + kw + q + 4];
            }
#pragma unroll
            for (int nt = 0; nt < 8; nt++) {
                int cb = warp_n * 64 + nt * 8;
                uint32_t b0 = Bs[(kw + q) * BS_STRIDE + cb + g];
                uint32_t b1 = Bs[(kw + q + 4) * BS_STRIDE + cb + g];
#pragma unroll
                for (int s = 0; s < 2; s++) {
                    asm volatile(
                        "mma.sync.aligned.m16n8k16.row.col.f32.bf16.bf16.f32 "
                        "{%0,%1,%2,%3}, {%4,%5,%6,%7}, {%8,%9}, {%0,%1,%2,%3};"
                        : "+f"(acc[s * 8 + nt][0]), "+f"(acc[s * 8 + nt][1]),
                          "+f"(acc[s * 8 + nt][2]), "+f"(acc[s * 8 + nt][3])
                        : "r"(af[s][0]), "r"(af[s][1]), "r"(af[s][2]), "r"(af[s][3]),
                          "r"(b0), "r"(b1));
                }
            }
        }
        __syncthreads();
    }

    int cgl = c0 + warp_n;
    float hv[2][2];
#pragma unroll
    for (int s = 0; s < 2; s++) {
#pragma unroll
        for (int rr = 0; rr < 2; rr++) {
            int node = n0 + warp_m * 32 + s * 16 + rr * 8 + g;
            hv[s][rr] = (node < Nn) ? g_hA[node * CLS + cgl] : 0.0f;
        }
    }
    float p[2][2] = {{0.f, 0.f}, {0.f, 0.f}};
#pragma unroll
    for (int nt = 0; nt < 8; nt++) {
#pragma unroll
        for (int cc = 0; cc < 2; cc++) {
            int h = nt * 8 + 2 * q + cc;
            int sidx = warp_n * 64 + h;
            float w0 = a1w0s[sidx], bb = a1bs[sidx], w2 = a2ws[sidx];
#pragma unroll
            for (int s = 0; s < 2; s++) {
                float z0 = fmaxf(acc[s * 8 + nt][cc] + hv[s][0] * w0 + bb, 0.0f);
                float z1 = fmaxf(acc[s * 8 + nt][2 + cc] + hv[s][1] * w0 + bb, 0.0f);
                p[s][0] += z0 * w2;
                p[s][1] += z1 * w2;
            }
        }
    }
#pragma unroll
    for (int s = 0; s < 2; s++) {
#pragma unroll
        for (int rr = 0; rr < 2; rr++) {
            float v = p[s][rr];
            v += __shfl_down_sync(0xffffffffu, v, 1, 4);
            v += __shfl_down_sync(0xffffffffu, v, 2, 4);
            if (q == 0)
                outsum[(warp_m * 32 + s * 16 + rr * 8 + g) * 4 + warp_n] = v;
        }
    }
    __syncthreads();
    {
        int nl = tid >> 2, cl = tid & 3;
        int node = n0 + nl;
        int cg2 = c0 + cl;
        if (node < Nn) {
            float v = outsum[nl * 4 + cl] + A2b[cg2];
            float gv = g_dis[node] * v;
            g_out0[node * CLS + cg2] = v;
            g_gA[node * CLS + cg2] = gv;
            g_dh0[node * CLS + cg2] = gv;
        }
    }
}

// ---------------- launch ----------------
extern "C" void kernel_launch(void* const* d_in, const int* in_sizes, int n_in,
                              void* d_out, int out_size) {
    const float* x     = (const float*)d_in[0];
    const void*  edges = d_in[1];
    const float* W1    = (const float*)d_in[2];
    const float* b1    = (const float*)d_in[3];
    const float* W2    = (const float*)d_in[4];
    const float* b2    = (const float*)d_in[5];
    const float* A1w   = (const float*)d_in[6];
    const float* A1b   = (const float*)d_in[7];
    const float* A2w   = (const float*)d_in[8];
    const float* A2b   = (const float*)d_in[9];

    degscan_kernel<<<PBLK, 256>>>(edges, x, A1w);
    fillmlp_kernel<<<9 * MLP_BLOCKS, 256>>>(edges, x, W1, b1, W2, b2);
    persist_diffuse<<<PBLK, 256>>>(0, nullptr);
    head_kernel<<<dim3((Nn + 63) / 64, 4), 256>>>(A1w, A1b, A2w, A2b);
    persist_diffuse<<<PBLK, 256>>>(1, (float*)d_out);
}

// round 16
// speedup vs baseline: 1.1838x; 1.1838x over previous
#include <cuda_runtime.h>
#include <cuda_bf16.h>
#include <cstdint>

#define Nn     100000
#define Ee     3200000
#define FEATS  256
#define CLS    16
#define HID    64
#define DEPTH  20
#define A1W_STRIDE (257*64)

#define FILL_BLOCKS 12500
#define MLP_BLOCKS  1563

#define PBLK   888     // persistent grid: 6 blocks/SM * 148 SMs
#define CHUNK  113     // ceil(Nn / PBLK)

#define BS_STRIDE 260  // B smem row stride (words), 1040B = 16B-aligned

// ---------------- scratch (static device globals; no allocation) ----------------
__device__ int      g_is64;
__device__ int      g_deg[Nn];       // must be zero at entry; persist chain2 re-zeroes
__device__ int      g_partial[PBLK];
__device__ int      g_rowptr[Nn + 1];
__device__ int      g_cursor[Nn];
__device__ int      g_col[Ee];       // src*4 sorted by dst (CSR by dst, float4-index pre-scaled)
__device__ float    g_dis[Nn];
__device__ float    g_dis2[Nn];
__device__ float    g_h0[Nn * CLS];
__device__ float    g_hA[Nn * CLS];
__device__ float    g_out0[Nn * CLS];
__device__ float    g_dh0[Nn * CLS];
__device__ float    g_gA[Nn * CLS];
__device__ float    g_gB[Nn * CLS];
__device__ uint32_t g_xbf[Nn * 128];        // x packed bf16x2: [node][kpair]
__device__ uint32_t g_bw[CLS * 128 * 64];   // A1w packed bf16x2: [class][kpair][h]

__device__ int          g_bar_count;
__device__ volatile int g_bar_sense;

// ---------------- helpers ----------------
__device__ __forceinline__ uint32_t pack_bf16(float lo, float hi) {
    __nv_bfloat162 h = __floats2bfloat162_rn(lo, hi);
    return *reinterpret_cast<uint32_t*>(&h);
}

__device__ __forceinline__ uint32_t smem_u32(const void* p) {
    return (uint32_t)__cvta_generic_to_shared(p);
}

__device__ __forceinline__ void cp16(uint32_t dst, const void* src, int sz) {
    asm volatile("cp.async.ca.shared.global [%0], [%1], 16, %2;"
                 :: "r"(dst), "l"(src), "r"(sz));
}

// random gather (16B) as two packed-f32x2 words; L1 no-allocate
__device__ __forceinline__ void ld_na2(const float4* p,
                                       unsigned long long& a, unsigned long long& b) {
    asm("ld.global.nc.L1::no_allocate.v2.u64 {%0,%1}, [%2];"
        : "=l"(a), "=l"(b) : "l"(p));
}

// random gather (16B) as float4; L1 no-allocate (remainder path)
__device__ __forceinline__ float4 ld_na(const float4* p) {
    float4 v;
    asm("ld.global.nc.L1::no_allocate.v4.f32 {%0,%1,%2,%3}, [%4];"
        : "=f"(v.x), "=f"(v.y), "=f"(v.z), "=f"(v.w) : "l"(p));
    return v;
}

// packed dual fp32 add (two independent rn adds in one instruction)
__device__ __forceinline__ unsigned long long addx2(unsigned long long a,
                                                    unsigned long long b) {
    unsigned long long o;
    asm("add.rn.f32x2 %0, %1, %2;" : "=l"(o) : "l"(a), "l"(b));
    return o;
}

__device__ __forceinline__ float2 unpk(unsigned long long v) {
    float2 r;
    asm("mov.b64 {%0,%1}, %2;" : "=f"(r.x), "=f"(r.y) : "l"(v));
    return r;
}

__device__ __forceinline__ void grid_sync(int* sense) {
    __syncthreads();
    if (threadIdx.x == 0) {
        int s = *sense ^ 1;
        *sense = s;
        __threadfence();
        if (atomicAdd(&g_bar_count, 1) == PBLK - 1) {
            g_bar_count = 0;
            __threadfence();
            g_bar_sense = s;
        } else {
            while (g_bar_sense != s) __nanosleep(128);
            __threadfence();
        }
    }
    __syncthreads();
}

// ------ persistent degree histogram + scan + bf16 pre-pack (one launch) ------
__global__ __launch_bounds__(256, 6) void degscan_kernel(
    const void* __restrict__ edges, const float* __restrict__ x,
    const float* __restrict__ A1w) {
    __shared__ int s_is64, s_sense, s_off;
    __shared__ int s_red[8];
    __shared__ int s_w[4];
    int tid = threadIdx.x;
    int lane = tid & 31, warp = tid >> 5;
    const int* e32 = (const int*)edges;

    if (tid < 32) {
        int nz = 0;
        for (int i = tid; i < 2048; i += 32) nz += (e32[2 * i + 1] != 0);
        for (int o = 16; o; o >>= 1) nz += __shfl_down_sync(0xffffffffu, nz, o);
        if (tid == 0) {
            s_is64 = (nz == 0) ? 1 : 0;
            if (blockIdx.x == 0) g_is64 = s_is64;
        }
    }
    if (tid == 0) s_sense = g_bar_sense;
    __syncthreads();
    int sense = s_sense;
    int is64 = s_is64;

    if (is64) {
        const long long* e64 = (const long long*)edges;
        for (long long e = (long long)blockIdx.x * 256 + tid; e < Ee; e += (long long)PBLK * 256)
            atomicAdd(&g_deg[(int)e64[Ee + e]], 1);
    } else {
        for (int e = blockIdx.x * 256 + tid; e < Ee; e += PBLK * 256)
            atomicAdd(&g_deg[e32[Ee + e]], 1);
    }
    for (int i = blockIdx.x * 256 + tid; i < Nn * 128; i += PBLK * 256) {
        float2 v = reinterpret_cast<const float2*>(x)[i];
        g_xbf[i] = pack_bf16(v.x, v.y);
    }
    for (int i = blockIdx.x * 256 + tid; i < CLS * 128 * 64; i += PBLK * 256) {
        int h = i & 63;
        int kp = (i >> 6) & 127;
        int cl = i >> 13;
        size_t base = (size_t)cl * A1W_STRIDE + (size_t)(1 + 2 * kp) * HID + h;
        g_bw[i] = pack_bf16(A1w[base], A1w[base + HID]);
    }
    grid_sync(&sense);

    int lo = blockIdx.x * CHUNK;
    int hi = min(lo + CHUNK, Nn);
    int n = lo + tid;
    int v = (tid < 128 && n < hi) ? g_deg[n] : 0;
    {
        int r = v;
        for (int o = 16; o; o >>= 1) r += __shfl_down_sync(0xffffffffu, r, o);
        if (lane == 0 && warp < 4) s_red[warp] = r;
    }
    __syncthreads();
    if (tid == 0) g_partial[blockIdx.x] = s_red[0] + s_red[1] + s_red[2] + s_red[3];
    grid_sync(&sense);

    {
        int ps = 0;
        for (int i = tid; i < blockIdx.x; i += 256) ps += g_partial[i];
        for (int o = 16; o; o >>= 1) ps += __shfl_down_sync(0xffffffffu, ps, o);
        if (lane == 0) s_red[warp] = ps;
    }
    __syncthreads();
    if (tid == 0) {
        int t = 0;
        for (int w = 0; w < 8; w++) t += s_red[w];
        s_off = t;
    }
    __syncthreads();
    int incl = v;
    for (int o = 1; o < 32; o <<= 1) {
        int u = __shfl_up_sync(0xffffffffu, incl, o);
        if (lane >= o) incl += u;
    }
    if (lane == 31 && warp < 4) s_w[warp] = incl;
    __syncthreads();
    if (tid < 128 && n < hi) {
        int woff = 0;
        for (int w = 0; w < warp; w++) woff += s_w[w];
        int excl = s_off + woff + incl - v;
        g_rowptr[n] = excl;
        g_cursor[n] = excl;
        float dv = (v > 0) ? rsqrtf((float)v) : 0.0f;
        g_dis[n] = dv;
        g_dis2[n] = dv * dv;
        if (n + 1 == Nn) g_rowptr[Nn] = excl + v;
    }
}

// ---------------- merged fill (CSR scatter, pre-scaled src*4) + MLP ----------------
#define MLP_NB 64
__global__ __launch_bounds__(256) void fillmlp_kernel(
    const void* __restrict__ edges,
    const float* __restrict__ x, const float* __restrict__ W1,
    const float* __restrict__ b1, const float* __restrict__ W2,
    const float* __restrict__ b2) {
    __shared__ float xs[MLP_NB][65];
    __shared__ float w1s[64][64];
    __shared__ float w2s[64][16];

    int m = blockIdx.x / 9, r = blockIdx.x % 9;
    int tid = threadIdx.x;

    if (r < 8) {
        int fb = m * 8 + r;
        if (fb >= FILL_BLOCKS) return;
        int e = fb * 256 + tid;
        if (e < Ee) {
            int is64 = g_is64;
            int s, d;
            if (is64) {
                s = (int)((const long long*)edges)[e];
                d = (int)((const long long*)edges)[(long long)Ee + e];
            } else {
                s = ((const int*)edges)[e];
                d = ((const int*)edges)[Ee + e];
            }
            int p = atomicAdd(&g_cursor[d], 1);
            g_col[p] = s * 4;   // pre-scaled float4 index
        }
        return;
    }

    if (m >= MLP_BLOCKS) return;
    int n0 = m * MLP_NB;
    int nq = tid >> 4;
    int jq = tid & 15;

    for (int i = tid; i < 64 * 16; i += 256) w2s[i >> 4][i & 15] = W2[i];

    float acc[4][4];
#pragma unroll
    for (int i = 0; i < 4; i++)
#pragma unroll
        for (int j = 0; j < 4; j++) acc[i][j] = 0.0f;

    for (int kc = 0; kc < FEATS; kc += 64) {
        for (int i = tid; i < 64 * 64; i += 256) {
            int n = i >> 6, k = i & 63;
            int gn = n0 + n;
            xs[n][k] = (gn < Nn) ? x[(size_t)gn * FEATS + kc + k] : 0.0f;
        }
        for (int i = tid; i < 64 * 64; i += 256) {
            int k = i >> 6, j = i & 63;
            w1s[k][j] = W1[(size_t)(kc + k) * HID + j];
        }
        __syncthreads();
#pragma unroll 8
        for (int k = 0; k < 64; k++) {
            float xv0 = xs[nq * 4 + 0][k];
            float xv1 = xs[nq * 4 + 1][k];
            float xv2 = xs[nq * 4 + 2][k];
            float xv3 = xs[nq * 4 + 3][k];
            float4 w = *reinterpret_cast<const float4*>(&w1s[k][jq * 4]);
            acc[0][0] += xv0 * w.x; acc[0][1] += xv0 * w.y; acc[0][2] += xv0 * w.z; acc[0][3] += xv0 * w.w;
            acc[1][0] += xv1 * w.x; acc[1][1] += xv1 * w.y; acc[1][2] += xv1 * w.z; acc[1][3] += xv1 * w.w;
            acc[2][0] += xv2 * w.x; acc[2][1] += xv2 * w.y; acc[2][2] += xv2 * w.z; acc[2][3] += xv2 * w.w;
            acc[3][0] += xv3 * w.x; acc[3][1] += xv3 * w.y; acc[3][2] += xv3 * w.z; acc[3][3] += xv3 * w.w;
        }
        __syncthreads();
    }
#pragma unroll
    for (int j = 0; j < 4; j++) {
        float bb = b1[jq * 4 + j];
#pragma unroll
        for (int i = 0; i < 4; i++)
            xs[nq * 4 + i][jq * 4 + j] = fmaxf(acc[i][j] + bb, 0.0f);
    }
    __syncthreads();
#pragma unroll
    for (int rr = 0; rr < 4; rr++) {
        int idx = tid * 4 + rr;
        int n = idx >> 4, c = idx & 15;
        float s = b2[c];
#pragma unroll 8
        for (int k = 0; k < 64; k++) s += xs[n][k] * w2s[k][c];
        int gn = n0 + n;
        if (gn < Nn) {
            float gv = g_dis[gn] * s;
            g_h0[gn * CLS + c] = s;
            g_gA[gn * CLS + c] = gv;
            g_dh0[gn * CLS + c] = gv;
        }
    }
}

// ------ persistent diffusion chain: quad gathers + packed f32x2 accumulation ------
// lane = (eg 0..7, q 0..3); eg owns edge quads [r0+4*eg+32j, +3].
// 4 col loads (one line) + 4 independent 16B gathers per iteration;
// accumulation uses add.rn.f32x2 (8 instr instead of 16 FADD).
__global__ __launch_bounds__(256, 6) void persist_diffuse(int d2, float* __restrict__ h_ext) {
    __shared__ int s_sense;
    int tid = threadIdx.x;
    int warp = tid >> 5;
    int lane = tid & 31;
    int eg = lane >> 2;
    int q  = lane & 3;

    int lo = blockIdx.x * CHUNK;
    int hi = min(lo + CHUNK, Nn);

    if (tid == 0) s_sense = g_bar_sense;
    __syncthreads();
    int sense = s_sense;

    for (int it = 0; it < DEPTH; it++) {
        const float4* __restrict__ gi4 =
            (const float4*)((it & 1) ? g_gB : g_gA);
        float* __restrict__ go = (it & 1) ? g_gA : g_gB;
        bool fin = (it == DEPTH - 1);

        for (int node = lo + warp; node < hi; node += 8) {
            int r0 = __ldg(&g_rowptr[node]);
            int r1 = __ldg(&g_rowptr[node + 1]);

            unsigned long long p00 = 0ULL, p01 = 0ULL, p10 = 0ULL, p11 = 0ULL;
            int e = r0 + eg * 4;
            for (; e + 3 < r1; e += 32) {
                int c0 = __ldg(&g_col[e]);
                int c1 = __ldg(&g_col[e + 1]);
                int c2 = __ldg(&g_col[e + 2]);
                int c3 = __ldg(&g_col[e + 3]);
                unsigned long long va0, vb0, va1, vb1, va2, vb2, va3, vb3;
                ld_na2(gi4 + c0 + q, va0, vb0);
                ld_na2(gi4 + c1 + q, va1, vb1);
                ld_na2(gi4 + c2 + q, va2, vb2);
                ld_na2(gi4 + c3 + q, va3, vb3);
                p00 = addx2(p00, va0); p01 = addx2(p01, vb0);
                p10 = addx2(p10, va1); p11 = addx2(p11, vb1);
                p00 = addx2(p00, va2); p01 = addx2(p01, vb2);
                p10 = addx2(p10, va3); p11 = addx2(p11, vb3);
            }
            float2 u00 = unpk(p00), u01 = unpk(p01), u10 = unpk(p10), u11 = unpk(p11);
            float4 s0 = make_float4(u00.x, u00.y, u01.x, u01.y);
            float4 s1 = make_float4(u10.x, u10.y, u11.x, u11.y);
            // partial quad (at most one lane per row, 1-3 edges)
            if (e < r1) {
                int c0 = __ldg(&g_col[e]);
                bool pr1 = (e + 1 < r1), pr2 = (e + 2 < r1);
                int c1 = pr1 ? __ldg(&g_col[e + 1]) : c0;
                int c2 = pr2 ? __ldg(&g_col[e + 2]) : c0;
                float4 v0 = ld_na(gi4 + c0 + q);
                float4 v1 = ld_na(gi4 + c1 + q);
                float4 v2 = ld_na(gi4 + c2 + q);
                s0.x += v0.x; s0.y += v0.y; s0.z += v0.z; s0.w += v0.w;
                if (pr1) { s1.x += v1.x; s1.y += v1.y; s1.z += v1.z; s1.w += v1.w; }
                if (pr2) { s0.x += v2.x; s0.y += v2.y; s0.z += v2.z; s0.w += v2.w; }
            }
            float4 acc;
            acc.x = s0.x + s1.x; acc.y = s0.y + s1.y;
            acc.z = s0.z + s1.z; acc.w = s0.w + s1.w;
#pragma unroll
            for (int mm = 16; mm >= 4; mm >>= 1) {
                acc.x += __shfl_xor_sync(0xffffffffu, acc.x, mm);
                acc.y += __shfl_xor_sync(0xffffffffu, acc.y, mm);
                acc.z += __shfl_xor_sync(0xffffffffu, acc.z, mm);
                acc.w += __shfl_xor_sync(0xffffffffu, acc.w, mm);
            }
            if (eg == 0) {
                if (!fin) {
                    float dd = __ldg(&g_dis2[node]);
                    float4 b = reinterpret_cast<const float4*>(g_dh0)[node * 4 + q];
                    float4 o;
                    o.x = 0.9f * dd * acc.x + 0.1f * b.x;
                    o.y = 0.9f * dd * acc.y + 0.1f * b.y;
                    o.z = 0.9f * dd * acc.z + 0.1f * b.z;
                    o.w = 0.9f * dd * acc.w + 0.1f * b.w;
                    reinterpret_cast<float4*>(go)[node * 4 + q] = o;
                } else {
                    float dv = __ldg(&g_dis[node]);
                    const float* h0 = d2 ? g_out0 : g_h0;
                    float* ho = d2 ? h_ext : g_hA;
                    float4 b = reinterpret_cast<const float4*>(h0)[node * 4 + q];
                    float4 o;
                    o.x = 0.9f * dv * acc.x + 0.1f * b.x;
                    o.y = 0.9f * dv * acc.y + 0.1f * b.y;
                    o.z = 0.9f * dv * acc.z + 0.1f * b.z;
                    o.w = 0.9f * dv * acc.w + 0.1f * b.w;
                    reinterpret_cast<float4*>(ho)[node * 4 + q] = o;
                }
            }
        }
        if (it != DEPTH - 1) grid_sync(&sense);
    }
    if (d2) {
        int n = blockIdx.x * 256 + tid;
        if (n < Nn) g_deg[n] = 0;
    }
}

// ------- fused head: bf16 MMA, cp.async double-buffered, 32x64 warp tiles ----
__global__ __launch_bounds__(256, 2) void head_kernel(
    const float* __restrict__ A1w, const float* __restrict__ A1b,
    const float* __restrict__ A2w, const float* __restrict__ A2b) {
    __shared__ uint32_t As32[2][64 * 20];
    __shared__ uint32_t Bs32[2][16 * BS_STRIDE];
    __shared__ float a1w0s[4 * 64];
    __shared__ float a1bs[4 * 64];
    __shared__ float a2ws[4 * 64];
    __shared__ float outsum[64 * 4];

    int tid = threadIdx.x;
    int warp = tid >> 5, lane = tid & 31;
    int g = lane >> 2, q = lane & 3;
    int warp_m = warp & 1;
    int warp_n = warp >> 1;
    int n0 = blockIdx.x * 64;
    int c0 = blockIdx.y * 4;

    for (int i = tid; i < 256; i += 256) {
        int cl = i >> 6, h = i & 63;
        a1w0s[i] = A1w[(size_t)(c0 + cl) * A1W_STRIDE + h];
        a1bs[i]  = A1b[(c0 + cl) * HID + h];
        a2ws[i]  = A2w[(c0 + cl) * HID + h];
    }

    int a_row = tid >> 2, a_w4 = tid & 3;
    int a_gn = n0 + a_row;
    int a_sz = (a_gn < Nn) ? 16 : 0;
    const uint32_t* a_src_base = g_xbf + (size_t)min(a_gn, Nn - 1) * 128 + a_w4 * 4;
    uint32_t a_dst_off = (a_row * 20 + a_w4 * 4) * 4;

    uint32_t b_dst_off[4];
    const uint32_t* b_src_base[4];
#pragma unroll
    for (int j = 0; j < 4; j++) {
        int u = tid + j * 256;
        int kp = u >> 6, cl = (u >> 4) & 3, h4 = u & 15;
        b_dst_off[j] = (kp * BS_STRIDE + cl * 64 + h4 * 4) * 4;
        b_src_base[j] = g_bw + ((size_t)(c0 + cl) * 128 + kp) * 64 + h4 * 4;
    }

    uint32_t As_base = smem_u32(&As32[0][0]);
    uint32_t Bs_base = smem_u32(&Bs32[0][0]);
    const uint32_t A_BUF = 64 * 20 * 4;
    const uint32_t B_BUF = 16 * BS_STRIDE * 4;

    float acc[16][4];
#pragma unroll
    for (int i = 0; i < 16; i++)
#pragma unroll
        for (int j = 0; j < 4; j++) acc[i][j] = 0.0f;

    {
        cp16(As_base + a_dst_off, a_src_base, a_sz);
#pragma unroll
        for (int j = 0; j < 4; j++) cp16(Bs_base + b_dst_off[j], b_src_base[j], 16);
        asm volatile("cp.async.commit_group;");
    }

    for (int c = 0; c < 8; c++) {
        if (c + 1 < 8) {
            int nb = (c + 1) & 1;
            cp16(As_base + nb * A_BUF + a_dst_off, a_src_base + (c + 1) * 16, a_sz);
#pragma unroll
            for (int j = 0; j < 4; j++)
                cp16(Bs_base + nb * B_BUF + b_dst_off[j], b_src_base[j] + (size_t)(c + 1) * 1024, 16);
            asm volatile("cp.async.commit_group;");
            asm volatile("cp.async.wait_group 1;");
        } else {
            asm volatile("cp.async.wait_group 0;");
        }
        __syncthreads();

        const uint32_t* As = As32[c & 1];
        const uint32_t* Bs = Bs32[c & 1];
#pragma unroll
        for (int kk = 0; kk < 2; kk++) {
            int kw = kk * 8;
            uint32_t af[2][4];
#pragma unroll
            for (int s = 0; s < 2; s++) {
                int ar = warp_m * 32 + s * 16;
                af[s][0] = As[(ar + g) * 20 + kw + q];
                af[s][1] = As[(ar + g + 8) * 20 + kw + q];
                af[s][2] = As[(ar + g) * 20 + kw + q + 4];
                af[s][3] = As[(ar + g + 8) * 20 + kw + q + 4];
            }
#pragma unroll
            for (int nt = 0; nt < 8; nt++) {
                int cb = warp_n * 64 + nt * 8;
                uint32_t b0 = Bs[(kw + q) * BS_STRIDE + cb + g];
                uint32_t b1 = Bs[(kw + q + 4) * BS_STRIDE + cb + g];
#pragma unroll
                for (int s = 0; s < 2; s++) {
                    asm volatile(
                        "mma.sync.aligned.m16n8k16.row.col.f32.bf16.bf16.f32 "
                        "{%0,%1,%2,%3}, {%4,%5,%6,%7}, {%8,%9}, {%0,%1,%2,%3};"
                        : "+f"(acc[s * 8 + nt][0]), "+f"(acc[s * 8 + nt][1]),
                          "+f"(acc[s * 8 + nt][2]), "+f"(acc[s * 8 + nt][3])
                        : "r"(af[s][0]), "r"(af[s][1]), "r"(af[s][2]), "r"(af[s][3]),
                          "r"(b0), "r"(b1));
                }
            }
        }
        __syncthreads();
    }

    int cgl = c0 + warp_n;
    float hv[2][2];
#pragma unroll
    for (int s = 0; s < 2; s++) {
#pragma unroll
        for (int rr = 0; rr < 2; rr++) {
            int node = n0 + warp_m * 32 + s * 16 + rr * 8 + g;
            hv[s][rr] = (node < Nn) ? g_hA[node * CLS + cgl] : 0.0f;
        }
    }
    float p[2][2] = {{0.f, 0.f}, {0.f, 0.f}};
#pragma unroll
    for (int nt = 0; nt < 8; nt++) {
#pragma unroll
        for (int cc = 0; cc < 2; cc++) {
            int h = nt * 8 + 2 * q + cc;
            int sidx = warp_n * 64 + h;
            float w0 = a1w0s[sidx], bb = a1bs[sidx], w2 = a2ws[sidx];
#pragma unroll
            for (int s = 0; s < 2; s++) {
                float z0 = fmaxf(acc[s * 8 + nt][cc] + hv[s][0] * w0 + bb, 0.0f);
                float z1 = fmaxf(acc[s * 8 + nt][2 + cc] + hv[s][1] * w0 + bb, 0.0f);
                p[s][0] += z0 * w2;
                p[s][1] += z1 * w2;
            }
        }
    }
#pragma unroll
    for (int s = 0; s < 2; s++) {
#pragma unroll
        for (int rr = 0; rr < 2; rr++) {
            float v = p[s][rr];
            v += __shfl_down_sync(0xffffffffu, v, 1, 4);
            v += __shfl_down_sync(0xffffffffu, v, 2, 4);
            if (q == 0)
                outsum[(warp_m * 32 + s * 16 + rr * 8 + g) * 4 + warp_n] = v;
        }
    }
    __syncthreads();
    {
        int nl = tid >> 2, cl = tid & 3;
        int node = n0 + nl;
        int cg2 = c0 + cl;
        if (node < Nn) {
            float v = outsum[nl * 4 + cl] + A2b[cg2];
            float gv = g_dis[node] * v;
            g_out0[node * CLS + cg2] = v;
            g_gA[node * CLS + cg2] = gv;
            g_dh0[node * CLS + cg2] = gv;
        }
    }
}

// ---------------- launch ----------------
extern "C" void kernel_launch(void* const* d_in, const int* in_sizes, int n_in,
                              void* d_out, int out_size) {
    const float* x     = (const float*)d_in[0];
    const void*  edges = d_in[1];
    const float* W1    = (const float*)d_in[2];
    const float* b1    = (const float*)d_in[3];
    const float* W2    = (const float*)d_in[4];
    const float* b2    = (const float*)d_in[5];
    const float* A1w   = (const float*)d_in[6];
    const float* A1b   = (const float*)d_in[7];
    const float* A2w   = (const float*)d_in[8];
    const float* A2b   = (const float*)d_in[9];

    degscan_kernel<<<PBLK, 256>>>(edges, x, A1w);
    fillmlp_kernel<<<9 * MLP_BLOCKS, 256>>>(edges, x, W1, b1, W2, b2);
    persist_diffuse<<<PBLK, 256>>>(0, nullptr);
    head_kernel<<<dim3((Nn + 63) / 64, 4), 256>>>(A1w, A1b, A2w, A2b);
    persist_diffuse<<<PBLK, 256>>>(1, (float*)d_out);
}